// round 12
// baseline (speedup 1.0000x reference)
#include <cuda_runtime.h>
#include <cuda_fp16.h>
#include <math.h>

#define NN 512
#define FF 64
#define SS 5
#define TT 32
#define NC 32       // sender chunks per receiver
#define CHUNK (NN/NC)   // 16
#define TSZ 16      // sender tile size == CHUNK: one tile per block
#define NPTS 2048   // wj table points
#define RMAX 16.0f

// -------- device scratch (no allocations allowed) --------
__device__ float  g_x0v[NN*FF];          // layer0: x0 only
__device__ float4 g_xv[NN*FF];           // layer1: {x0, x1x, x1y, x1z}
__device__ float4 g_t0a[NPTS*FF];        // L0 table: {v0,v1,v2, h2(s0,s1)}
__device__ __half g_t0s2[NPTS*FF];       // L0 table: s2
__device__ float4 g_t5a[NPTS*FF];        // L1 table: {v0,v1,v2,v3}
__device__ float4 g_t5b[NPTS*FF];        // L1 table: {v4, h2(s0,s1), h2(s2,s3), h2(s4,0)}
__device__ float  g_Apart[NC*NN*9*FF];   // partial segment sums (37.7MB, L2-resident)
__device__ float  g_pos[NN*3];           // current positions

__device__ __forceinline__ float2 h2f(float bits) {
    __half2 h; unsigned u = __float_as_uint(bits);
    h = *(__half2*)&u;
    return __half22float2(h);
}
__device__ __forceinline__ float packh2(float a, float b) {
    __half2 h = __floats2half2_rn(a, b);
    return __uint_as_float(*(unsigned*)&h);
}

// -------- fused: wj tables (both layers) + embed/layer0-linear --------
// blocks [0, 2*NPTS/8)           : table build (layer = bx>>8 for NPTS=2048)
// blocks [2*NPTS/8, +NN/8)       : embed + layer0 linear (8 nodes/block)
#define NB_TAB (2*(NPTS/8))
__global__ void k_prep(const float* __restrict__ We1, const float* __restrict__ be1,
                       const float* __restrict__ We2,
                       const float* __restrict__ pos_in, const int* __restrict__ nodef,
                       const float* __restrict__ te, const float* __restrict__ W_embed,
                       const float* __restrict__ b_embed, const float* __restrict__ Wl0) {
    int f = threadIdx.x, ty = threadIdx.y;
    int bx = blockIdx.x;
    if (bx < NB_TAB) {
        // ---- table build: 8 points per block ----
        __shared__ float sW[32*320];    // We2 repacked: [k][f*5+j]
        __shared__ float sHe[9][32];
        int layer = bx / (NPTS/8);
        int p0 = (bx % (NPTS/8)) * 8;
        int tid = ty*64 + f;
        const float hstep = RMAX / (float)(NPTS-1);
        const float* We2l = We2 + layer*32*384;
        const float* We1l = We1 + layer*32;
        const float* be1l = be1 + layer*32;

        for (int idx = tid; idx < 32*320; idx += 512) {
            int k = idx / 320, cc = idx % 320;
            sW[idx] = We2l[k*384 + (cc/5)*6 + (cc%5)];
        }
        for (int idx = tid; idx < 9*32; idx += 512) {
            int row = idx >> 5, k = idx & 31;
            int p = p0 + row; if (p > NPTS-1) p = NPTS-1;
            float x = fmaf((float)p * hstep, We1l[k], be1l[k]);
            sHe[row][k] = x / (1.0f + expf(-x));
        }
        __syncthreads();

        float va[5] = {0,0,0,0,0}, vb[5] = {0,0,0,0,0};
        #pragma unroll 4
        for (int k = 0; k < 32; k++) {
            float hA = sHe[ty][k], hB = sHe[ty+1][k];
            const float* w = &sW[k*320 + f*5];
            #pragma unroll
            for (int j = 0; j < 5; j++) {
                va[j] = fmaf(hA, w[j], va[j]);
                vb[j] = fmaf(hB, w[j], vb[j]);
            }
        }
        int ti = (p0 + ty)*FF + f;
        if (layer == 0) {
            g_t0a[ti] = make_float4(va[0], va[1], va[2],
                                    packh2(vb[0]-va[0], vb[1]-va[1]));
            g_t0s2[ti] = __float2half(vb[2]-va[2]);
        } else {
            g_t5a[ti] = make_float4(va[0], va[1], va[2], va[3]);
            g_t5b[ti] = make_float4(va[4],
                                    packh2(vb[0]-va[0], vb[1]-va[1]),
                                    packh2(vb[2]-va[2], vb[3]-va[3]),
                                    packh2(vb[4]-va[4], 0.f));
        }
    } else {
        // ---- embed + layer0 linear: 8 nodes per block ----
        __shared__ float sH[8][FF];
        int n = (bx - NB_TAB)*8 + ty;
        if (f < 3) g_pos[n*3+f] = pos_in[n*3+f];
        int sp = nodef[n] - 1;
        float h = W_embed[sp*FF + f] + b_embed[f];
        #pragma unroll
        for (int t = 0; t < TT; t++) h = fmaf(te[t], W_embed[(SS+t)*FF + f], h);
        sH[ty][f] = h;
        __syncthreads();
        float a0 = 0.f;
        #pragma unroll 8
        for (int g = 0; g < FF; g++) a0 = fmaf(sH[ty][g], Wl0[g*FF + f], a0);
        g_x0v[n*FF + f] = a0;
    }
}

// -------- edge kernel: single 16-sender tile per block --------
template<int NJ>
__global__ void __launch_bounds__(64) k_edge() {
    const int r = blockIdx.x, c = blockIdx.y, f = threadIdx.x;
    __shared__ float sY1[TSZ][3];
    __shared__ float sY2[TSZ][5];
    __shared__ int   sIdx[TSZ];
    __shared__ float sFrac[TSZ];
    __shared__ float sVal[TSZ];

    const int base = c * CHUNK;
    if (f < TSZ) {
        const float prx = g_pos[r*3+0], pry = g_pos[r*3+1], prz = g_pos[r*3+2];
        const float tscale = (float)(NPTS-1) / RMAX;
        int s = base + f;
        float vx = prx - g_pos[s*3+0];
        float vy = pry - g_pos[s*3+1];
        float vz = prz - g_pos[s*3+2];
        float r2 = vx*vx + vy*vy + vz*vz;
        int ok = (s != r);
        float inv = ok ? rsqrtf(r2) : 0.0f;
        float rl = r2 * inv;
        float ux = vx*inv, uy = vy*inv, uz = vz*inv;
        float t = fminf(rl * tscale, (float)NPTS - 1.001f);
        int i = (int)t;
        sIdx[f]  = i;
        sFrac[f] = t - (float)i;
        sVal[f]  = ok ? 1.0f : 0.0f;
        const float s3  = 1.7320508075688772f;
        const float s5h = 0.5f * 2.2360679774997896f;
        const float s15 = 3.8729833462074170f;
        const float s15h = 0.5f * 3.8729833462074170f;
        sY1[f][0] = s3*ux; sY1[f][1] = s3*uy; sY1[f][2] = s3*uz;
        sY2[f][0] = s15*ux*uy;
        sY2[f][1] = s15*uy*uz;
        sY2[f][2] = s5h*(3.f*uz*uz - 1.f);
        sY2[f][3] = s15*ux*uz;
        sY2[f][4] = s15h*(ux*ux - uy*uy);
    }
    __syncthreads();

    float acc[9];
    #pragma unroll
    for (int ch = 0; ch < 9; ch++) acc[ch] = 0.f;

    #pragma unroll 4
    for (int sl = 0; sl < TSZ; sl++) {
        int s = base + sl;
        int i = sIdx[sl];
        float fr = sFrac[sl], val = sVal[sl];
        int ti = i*FF + f;

        float wj0, wj1, wj2, wj3 = 0.f, wj4 = 0.f;
        float a0v, a1x = 0.f, a1y = 0.f, a1z = 0.f;
        if (NJ > 3) {
            float4 A = g_t5a[ti];
            float4 B = g_t5b[ti];
            float2 s01 = h2f(B.y);
            float2 s23 = h2f(B.z);
            float2 s4p = h2f(B.w);
            wj0 = fmaf(fr, s01.x, A.x);
            wj1 = fmaf(fr, s01.y, A.y);
            wj2 = fmaf(fr, s23.x, A.z);
            wj3 = fmaf(fr, s23.y, A.w);
            wj4 = fmaf(fr, s4p.x, B.x);
            float4 xv = g_xv[s*FF + f];
            a0v = xv.x * val;
            a1x = xv.y * val; a1y = xv.z * val; a1z = xv.w * val;
        } else {
            float4 A = g_t0a[ti];
            float2 s01 = h2f(A.w);
            float s2 = __half2float(g_t0s2[ti]);
            wj0 = fmaf(fr, s01.x, A.x);
            wj1 = fmaf(fr, s01.y, A.y);
            wj2 = fmaf(fr, s2,    A.z);
            a0v = g_x0v[s*FF + f] * val;
        }

        float Y1x = sY1[sl][0], Y1y = sY1[sl][1], Y1z = sY1[sl][2];
        acc[0] = fmaf(wj0, a0v, acc[0]);
        float w1a = wj1 * a0v;
        acc[1] = fmaf(w1a, Y1x, acc[1]);
        acc[2] = fmaf(w1a, Y1y, acc[2]);
        acc[3] = fmaf(w1a, Y1z, acc[3]);
        float w2a = wj2 * a0v;
        acc[4] = fmaf(w2a, sY2[sl][0], acc[4]);
        acc[5] = fmaf(w2a, sY2[sl][1], acc[5]);
        acc[6] = fmaf(w2a, sY2[sl][2], acc[6]);
        acc[7] = fmaf(w2a, sY2[sl][3], acc[7]);
        acc[8] = fmaf(w2a, sY2[sl][4], acc[8]);
        if (NJ > 3) {
            float d1 = a1x*Y1x + a1y*Y1y + a1z*Y1z;
            acc[0] = fmaf(wj3, d1, acc[0]);
            float crx = a1y*Y1z - a1z*Y1y;
            float cry = a1z*Y1x - a1x*Y1z;
            float crz = a1x*Y1y - a1y*Y1x;
            acc[1] = fmaf(wj4, crx, acc[1]);
            acc[2] = fmaf(wj4, cry, acc[2]);
            acc[3] = fmaf(wj4, crz, acc[3]);
        }
    }
    #pragma unroll
    for (int ch = 0; ch < 9; ch++)
        g_Apart[((c*NN + r)*9 + ch)*FF + f] = acc[ch];
}

// -------- node update (4 nodes / block); final layer also writes output --------
template<bool DO_LIN>
__global__ void k_node(const int* __restrict__ nodef,
                       const float* __restrict__ Wp0, const float* __restrict__ Wp1,
                       const float* __restrict__ Wr1, const float* __restrict__ br1,
                       const float* __restrict__ Wr2g, const float* __restrict__ WlinNext,
                       const float* __restrict__ pos_in, float* __restrict__ out) {
    int ty = threadIdx.y, f = threadIdx.x;
    int n = blockIdx.x*4 + ty;
    float A[9];
    #pragma unroll
    for (int ch = 0; ch < 9; ch++) A[ch] = 0.f;
    #pragma unroll 8
    for (int c = 0; c < NC; c++) {
        #pragma unroll
        for (int ch = 0; ch < 9; ch++)
            A[ch] += g_Apart[((c*NN + n)*9 + ch)*FF + f];
    }
    #pragma unroll
    for (int ch = 0; ch < 9; ch++) A[ch] *= (1.0f/511.0f);

    float A0 = A[0];
    float n1 = A[1]*A[1] + A[2]*A[2] + A[3]*A[3];
    float n2 = A[4]*A[4] + A[5]*A[5] + A[6]*A[6] + A[7]*A[7] + A[8]*A[8];
    int sp = nodef[n] - 1;
    const float* w0 = Wp0 + (sp*FF + f)*6;
    float A02 = A0*A0;
    float out0 = w0[0]*A0 + w0[1]*A02 + w0[2]*A02*A0 + w0[3]*n1 + w0[4]*n2 + w0[5]*A0*n1;
    const float* w1 = Wp1 + (sp*FF + f)*3;
    float gp = w1[0] + w1[1]*A0 + w1[2]*A02;
    float o1x = gp*A[1], o1y = gp*A[2], o1z = gp*A[3];

    __shared__ float sO[4][FF];
    __shared__ float sV[4][3][FF];
    sO[ty][f] = out0;
    sV[ty][0][f] = o1x; sV[ty][1][f] = o1y; sV[ty][2][f] = o1z;
    __syncthreads();

    if (DO_LIN) {
        float a0 = 0.f, a1x = 0.f, a1y = 0.f, a1z = 0.f;
        #pragma unroll 8
        for (int g = 0; g < FF; g++) {
            float wa = WlinNext[g*FF + f];
            float wb = WlinNext[FF*FF + g*FF + f];
            a0  = fmaf(sO[ty][g],    wa, a0);
            a1x = fmaf(sV[ty][0][g], wb, a1x);
            a1y = fmaf(sV[ty][1][g], wb, a1y);
            a1z = fmaf(sV[ty][2][g], wb, a1z);
        }
        g_xv[n*FF + f] = make_float4(a0, a1x, a1y, a1z);
    }

    float hx = br1[f];
    #pragma unroll 8
    for (int g = 0; g < FF; g++) hx = fmaf(sO[ty][g], Wr1[g*FF + f], hx);
    float hr = hx / (1.0f + expf(-hx));
    __shared__ float sH[4][FF];
    sH[ty][f] = hr;
    __syncthreads();
    float gate = 0.f;
    #pragma unroll 8
    for (int m = 0; m < FF; m++) gate = fmaf(sH[ty][m], Wr2g[m*FF + f], gate);

    __shared__ float sRed[4][3][FF];
    sRed[ty][0][f] = gate*o1x; sRed[ty][1][f] = gate*o1y; sRed[ty][2][f] = gate*o1z;
    __syncthreads();
    if (f < 3) {
        float v = 0.f;
        for (int g = 0; g < FF; g++) v += sRed[ty][f][g];
        if (DO_LIN) {
            g_pos[n*3 + f] += v;   // deterministic: one thread per component
        } else {
            // final layer: emit (pos + v) - pos0 directly
            out[n*3 + f] = g_pos[n*3 + f] + v - pos_in[n*3 + f];
        }
    }
}

extern "C" void kernel_launch(void* const* d_in, const int* in_sizes, int n_in,
                              void* d_out, int out_size) {
    const float* positions = (const float*)d_in[0];
    const int*   nodef     = (const int*)  d_in[1];
    const float* te        = (const float*)d_in[2];
    // d_in[3]/[4] = senders/receivers: fully connected, structure used directly
    const float* W_embed   = (const float*)d_in[5];
    const float* b_embed   = (const float*)d_in[6];
    const float* W_lin     = (const float*)d_in[7];
    const float* W_e1      = (const float*)d_in[8];
    const float* b_e1      = (const float*)d_in[9];
    const float* W_e2      = (const float*)d_in[10];
    const float* Wp0       = (const float*)d_in[11];
    const float* Wp1       = (const float*)d_in[12];
    const float* Wr1       = (const float*)d_in[13];
    const float* br1       = (const float*)d_in[14];
    // d_in[15] = Wr2s: unused by the reference
    const float* Wr2g      = (const float*)d_in[16];
    float* out = (float*)d_out;

    dim3 b4(64, 4), b8(64, 8);

    // tables (both layers) + embed/linear0, one launch
    k_prep<<<NB_TAB + NN/8, b8>>>(W_e1, b_e1, W_e2,
                                  positions, nodef, te, W_embed, b_embed, W_lin);

    // layer 0 (s1 == 0 -> only j in {0,1,2})
    k_edge<3><<<dim3(NN, NC), 64>>>();
    k_node<true><<<NN/4, b4>>>(nodef, Wp0, Wp1, Wr1, br1, Wr2g,
                               W_lin + 3*FF*FF, positions, out);

    // layer 1 (j in {0..4}; j==5 multiplies an identically-zero term)
    k_edge<5><<<dim3(NN, NC), 64>>>();
    k_node<false><<<NN/4, b4>>>(nodef, Wp0 + SS*FF*6, Wp1 + SS*FF*3,
                                Wr1 + FF*FF, br1 + FF, Wr2g + FF*FF,
                                nullptr, positions, out);
}

// round 13
// speedup vs baseline: 1.1467x; 1.1467x over previous
#include <cuda_runtime.h>
#include <cuda_fp16.h>
#include <math.h>

#define NN 512
#define FF 64
#define SS 5
#define TT 32
#define NC 16       // sender chunks per receiver
#define CHUNK (NN/NC)   // 32
#define TSZ 32      // sender tile size == CHUNK: one tile per block
#define NPTS 2048   // wj table points
#define RMAX 16.0f

// -------- device scratch (no allocations allowed) --------
__device__ float  g_x0v[NN*FF];          // layer0: x0 only
__device__ float4 g_xv[NN*FF];           // layer1: {x0, x1x, x1y, x1z}
__device__ float4 g_t0a[NPTS*FF];        // L0 table: {v0,v1,v2, h2(s0,s1)}
__device__ __half g_t0s2[NPTS*FF];       // L0 table: s2
__device__ float4 g_t5a[NPTS*FF];        // L1 table: {v0,v1,v2,v3}
__device__ float4 g_t5b[NPTS*FF];        // L1 table: {v4, h2(s0,s1), h2(s2,s3), h2(s4,0)}
__device__ float  g_Apart[NC*NN*9*FF];   // partial segment sums (18.9MB, L2-resident)
__device__ float  g_pos[NN*3];           // current positions

__device__ __forceinline__ float2 h2f(float bits) {
    __half2 h; unsigned u = __float_as_uint(bits);
    h = *(__half2*)&u;
    return __half22float2(h);
}
__device__ __forceinline__ float packh2(float a, float b) {
    __half2 h = __floats2half2_rn(a, b);
    return __uint_as_float(*(unsigned*)&h);
}

// -------- fused: wj tables (both layers) + embed/layer0-linear --------
#define NB_TAB (2*(NPTS/8))
__global__ void k_prep(const float* __restrict__ We1, const float* __restrict__ be1,
                       const float* __restrict__ We2,
                       const float* __restrict__ pos_in, const int* __restrict__ nodef,
                       const float* __restrict__ te, const float* __restrict__ W_embed,
                       const float* __restrict__ b_embed, const float* __restrict__ Wl0) {
    int f = threadIdx.x, ty = threadIdx.y;
    int bx = blockIdx.x;
    if (bx < NB_TAB) {
        __shared__ float sW[32*320];    // We2 repacked: [k][f*5+j]
        __shared__ float sHe[9][32];
        int layer = bx / (NPTS/8);
        int p0 = (bx % (NPTS/8)) * 8;
        int tid = ty*64 + f;
        const float hstep = RMAX / (float)(NPTS-1);
        const float* We2l = We2 + layer*32*384;
        const float* We1l = We1 + layer*32;
        const float* be1l = be1 + layer*32;

        for (int idx = tid; idx < 32*320; idx += 512) {
            int k = idx / 320, cc = idx % 320;
            sW[idx] = We2l[k*384 + (cc/5)*6 + (cc%5)];
        }
        for (int idx = tid; idx < 9*32; idx += 512) {
            int row = idx >> 5, k = idx & 31;
            int p = p0 + row; if (p > NPTS-1) p = NPTS-1;
            float x = fmaf((float)p * hstep, We1l[k], be1l[k]);
            sHe[row][k] = x / (1.0f + expf(-x));
        }
        __syncthreads();

        float va[5] = {0,0,0,0,0}, vb[5] = {0,0,0,0,0};
        #pragma unroll 4
        for (int k = 0; k < 32; k++) {
            float hA = sHe[ty][k], hB = sHe[ty+1][k];
            const float* w = &sW[k*320 + f*5];
            #pragma unroll
            for (int j = 0; j < 5; j++) {
                va[j] = fmaf(hA, w[j], va[j]);
                vb[j] = fmaf(hB, w[j], vb[j]);
            }
        }
        int ti = (p0 + ty)*FF + f;
        if (layer == 0) {
            g_t0a[ti] = make_float4(va[0], va[1], va[2],
                                    packh2(vb[0]-va[0], vb[1]-va[1]));
            g_t0s2[ti] = __float2half(vb[2]-va[2]);
        } else {
            g_t5a[ti] = make_float4(va[0], va[1], va[2], va[3]);
            g_t5b[ti] = make_float4(va[4],
                                    packh2(vb[0]-va[0], vb[1]-va[1]),
                                    packh2(vb[2]-va[2], vb[3]-va[3]),
                                    packh2(vb[4]-va[4], 0.f));
        }
    } else {
        __shared__ float sH[8][FF];
        int n = (bx - NB_TAB)*8 + ty;
        if (f < 3) g_pos[n*3+f] = pos_in[n*3+f];
        int sp = nodef[n] - 1;
        float h = W_embed[sp*FF + f] + b_embed[f];
        #pragma unroll
        for (int t = 0; t < TT; t++) h = fmaf(te[t], W_embed[(SS+t)*FF + f], h);
        sH[ty][f] = h;
        __syncthreads();
        float a0 = 0.f;
        #pragma unroll 8
        for (int g = 0; g < FF; g++) a0 = fmaf(sH[ty][g], Wl0[g*FF + f], a0);
        g_x0v[n*FF + f] = a0;
    }
}

// -------- edge kernel: single 32-sender tile per block --------
template<int NJ>
__global__ void __launch_bounds__(64) k_edge() {
    const int r = blockIdx.x, c = blockIdx.y, f = threadIdx.x;
    __shared__ float sY1[TSZ][3];
    __shared__ float sY2[TSZ][5];
    __shared__ int   sIdx[TSZ];
    __shared__ float sFrac[TSZ];
    __shared__ float sVal[TSZ];

    const int base = c * CHUNK;
    if (f < TSZ) {
        const float prx = g_pos[r*3+0], pry = g_pos[r*3+1], prz = g_pos[r*3+2];
        const float tscale = (float)(NPTS-1) / RMAX;
        int s = base + f;
        float vx = prx - g_pos[s*3+0];
        float vy = pry - g_pos[s*3+1];
        float vz = prz - g_pos[s*3+2];
        float r2 = vx*vx + vy*vy + vz*vz;
        int ok = (s != r);
        float inv = ok ? rsqrtf(r2) : 0.0f;
        float rl = r2 * inv;
        float ux = vx*inv, uy = vy*inv, uz = vz*inv;
        float t = fminf(rl * tscale, (float)NPTS - 1.001f);
        int i = (int)t;
        sIdx[f]  = i;
        sFrac[f] = t - (float)i;
        sVal[f]  = ok ? 1.0f : 0.0f;
        const float s3  = 1.7320508075688772f;
        const float s5h = 0.5f * 2.2360679774997896f;
        const float s15 = 3.8729833462074170f;
        const float s15h = 0.5f * 3.8729833462074170f;
        sY1[f][0] = s3*ux; sY1[f][1] = s3*uy; sY1[f][2] = s3*uz;
        sY2[f][0] = s15*ux*uy;
        sY2[f][1] = s15*uy*uz;
        sY2[f][2] = s5h*(3.f*uz*uz - 1.f);
        sY2[f][3] = s15*ux*uz;
        sY2[f][4] = s15h*(ux*ux - uy*uy);
    }
    __syncthreads();

    float acc[9];
    #pragma unroll
    for (int ch = 0; ch < 9; ch++) acc[ch] = 0.f;

    #pragma unroll 4
    for (int sl = 0; sl < TSZ; sl++) {
        int s = base + sl;
        int i = sIdx[sl];
        float fr = sFrac[sl], val = sVal[sl];
        int ti = i*FF + f;

        float wj0, wj1, wj2, wj3 = 0.f, wj4 = 0.f;
        float a0v, a1x = 0.f, a1y = 0.f, a1z = 0.f;
        if (NJ > 3) {
            float4 A = g_t5a[ti];
            float4 B = g_t5b[ti];
            float2 s01 = h2f(B.y);
            float2 s23 = h2f(B.z);
            float2 s4p = h2f(B.w);
            wj0 = fmaf(fr, s01.x, A.x);
            wj1 = fmaf(fr, s01.y, A.y);
            wj2 = fmaf(fr, s23.x, A.z);
            wj3 = fmaf(fr, s23.y, A.w);
            wj4 = fmaf(fr, s4p.x, B.x);
            float4 xv = g_xv[s*FF + f];
            a0v = xv.x * val;
            a1x = xv.y * val; a1y = xv.z * val; a1z = xv.w * val;
        } else {
            float4 A = g_t0a[ti];
            float2 s01 = h2f(A.w);
            float s2 = __half2float(g_t0s2[ti]);
            wj0 = fmaf(fr, s01.x, A.x);
            wj1 = fmaf(fr, s01.y, A.y);
            wj2 = fmaf(fr, s2,    A.z);
            a0v = g_x0v[s*FF + f] * val;
        }

        float Y1x = sY1[sl][0], Y1y = sY1[sl][1], Y1z = sY1[sl][2];
        acc[0] = fmaf(wj0, a0v, acc[0]);
        float w1a = wj1 * a0v;
        acc[1] = fmaf(w1a, Y1x, acc[1]);
        acc[2] = fmaf(w1a, Y1y, acc[2]);
        acc[3] = fmaf(w1a, Y1z, acc[3]);
        float w2a = wj2 * a0v;
        acc[4] = fmaf(w2a, sY2[sl][0], acc[4]);
        acc[5] = fmaf(w2a, sY2[sl][1], acc[5]);
        acc[6] = fmaf(w2a, sY2[sl][2], acc[6]);
        acc[7] = fmaf(w2a, sY2[sl][3], acc[7]);
        acc[8] = fmaf(w2a, sY2[sl][4], acc[8]);
        if (NJ > 3) {
            float d1 = a1x*Y1x + a1y*Y1y + a1z*Y1z;
            acc[0] = fmaf(wj3, d1, acc[0]);
            float crx = a1y*Y1z - a1z*Y1y;
            float cry = a1z*Y1x - a1x*Y1z;
            float crz = a1x*Y1y - a1y*Y1x;
            acc[1] = fmaf(wj4, crx, acc[1]);
            acc[2] = fmaf(wj4, cry, acc[2]);
            acc[3] = fmaf(wj4, crz, acc[3]);
        }
    }
    #pragma unroll
    for (int ch = 0; ch < 9; ch++)
        g_Apart[((c*NN + r)*9 + ch)*FF + f] = acc[ch];
}

// -------- node update: one node / block, ty-parallel reduction --------
template<bool DO_LIN>
__global__ void k_node(const int* __restrict__ nodef,
                       const float* __restrict__ Wp0, const float* __restrict__ Wp1,
                       const float* __restrict__ Wr1, const float* __restrict__ br1,
                       const float* __restrict__ Wr2g, const float* __restrict__ WlinNext,
                       const float* __restrict__ pos_in, float* __restrict__ out) {
    int ty = threadIdx.y, f = threadIdx.x;
    int n = blockIdx.x;

    // ---- ty-parallel partial reduction: each ty sums NC/4 chunks ----
    __shared__ float sA[4][9][FF];
    {
        float P[9];
        #pragma unroll
        for (int ch = 0; ch < 9; ch++) P[ch] = 0.f;
        #pragma unroll
        for (int cc = 0; cc < NC/4; cc++) {
            int c = ty*(NC/4) + cc;
            #pragma unroll
            for (int ch = 0; ch < 9; ch++)
                P[ch] += g_Apart[((c*NN + n)*9 + ch)*FF + f];
        }
        #pragma unroll
        for (int ch = 0; ch < 9; ch++) sA[ty][ch][f] = P[ch];
    }
    __syncthreads();

    __shared__ float sO[FF];
    __shared__ float sV[3][FF];
    __shared__ float sH[FF];
    __shared__ float sRed[3][FF];
    __shared__ float sGate[FF];

    if (ty == 0) {
        float A[9];
        #pragma unroll
        for (int ch = 0; ch < 9; ch++)
            A[ch] = (sA[0][ch][f] + sA[1][ch][f] + sA[2][ch][f] + sA[3][ch][f])
                    * (1.0f/511.0f);
        float A0 = A[0];
        float n1 = A[1]*A[1] + A[2]*A[2] + A[3]*A[3];
        float n2 = A[4]*A[4] + A[5]*A[5] + A[6]*A[6] + A[7]*A[7] + A[8]*A[8];
        int sp = nodef[n] - 1;
        const float* w0 = Wp0 + (sp*FF + f)*6;
        float A02 = A0*A0;
        float out0 = w0[0]*A0 + w0[1]*A02 + w0[2]*A02*A0
                   + w0[3]*n1 + w0[4]*n2 + w0[5]*A0*n1;
        const float* w1 = Wp1 + (sp*FF + f)*3;
        float gp = w1[0] + w1[1]*A0 + w1[2]*A02;
        sO[f] = out0;
        sV[0][f] = gp*A[1]; sV[1][f] = gp*A[2]; sV[2][f] = gp*A[3];
    }
    __syncthreads();

    // two independent matvecs on different ty groups
    if (ty == 1 && DO_LIN) {
        float a0 = 0.f, a1x = 0.f, a1y = 0.f, a1z = 0.f;
        #pragma unroll 8
        for (int g = 0; g < FF; g++) {
            float wa = WlinNext[g*FF + f];
            float wb = WlinNext[FF*FF + g*FF + f];
            a0  = fmaf(sO[g],    wa, a0);
            a1x = fmaf(sV[0][g], wb, a1x);
            a1y = fmaf(sV[1][g], wb, a1y);
            a1z = fmaf(sV[2][g], wb, a1z);
        }
        g_xv[n*FF + f] = make_float4(a0, a1x, a1y, a1z);
    }
    if (ty == 0) {
        float hx = br1[f];
        #pragma unroll 8
        for (int g = 0; g < FF; g++) hx = fmaf(sO[g], Wr1[g*FF + f], hx);
        sH[f] = hx / (1.0f + expf(-hx));
    }
    __syncthreads();
    if (ty == 0) {
        float gate = 0.f;
        #pragma unroll 8
        for (int m = 0; m < FF; m++) gate = fmaf(sH[m], Wr2g[m*FF + f], gate);
        sGate[f] = gate;
        sRed[0][f] = gate*sV[0][f];
        sRed[1][f] = gate*sV[1][f];
        sRed[2][f] = gate*sV[2][f];
    }
    __syncthreads();
    if (ty == 0 && f < 3) {
        float v = 0.f;
        for (int g = 0; g < FF; g++) v += sRed[f][g];
        if (DO_LIN) {
            g_pos[n*3 + f] += v;   // deterministic: one thread per component
        } else {
            out[n*3 + f] = g_pos[n*3 + f] + v - pos_in[n*3 + f];
        }
    }
}

extern "C" void kernel_launch(void* const* d_in, const int* in_sizes, int n_in,
                              void* d_out, int out_size) {
    const float* positions = (const float*)d_in[0];
    const int*   nodef     = (const int*)  d_in[1];
    const float* te        = (const float*)d_in[2];
    // d_in[3]/[4] = senders/receivers: fully connected, structure used directly
    const float* W_embed   = (const float*)d_in[5];
    const float* b_embed   = (const float*)d_in[6];
    const float* W_lin     = (const float*)d_in[7];
    const float* W_e1      = (const float*)d_in[8];
    const float* b_e1      = (const float*)d_in[9];
    const float* W_e2      = (const float*)d_in[10];
    const float* Wp0       = (const float*)d_in[11];
    const float* Wp1       = (const float*)d_in[12];
    const float* Wr1       = (const float*)d_in[13];
    const float* br1       = (const float*)d_in[14];
    // d_in[15] = Wr2s: unused by the reference
    const float* Wr2g      = (const float*)d_in[16];
    float* out = (float*)d_out;

    dim3 b4(64, 4), b8(64, 8);

    // tables (both layers) + embed/linear0, one launch
    k_prep<<<NB_TAB + NN/8, b8>>>(W_e1, b_e1, W_e2,
                                  positions, nodef, te, W_embed, b_embed, W_lin);

    // layer 0 (s1 == 0 -> only j in {0,1,2})
    k_edge<3><<<dim3(NN, NC), 64>>>();
    k_node<true><<<NN, b4>>>(nodef, Wp0, Wp1, Wr1, br1, Wr2g,
                             W_lin + 3*FF*FF, positions, out);

    // layer 1 (j in {0..4}; j==5 multiplies an identically-zero term)
    k_edge<5><<<dim3(NN, NC), 64>>>();
    k_node<false><<<NN, b4>>>(nodef, Wp0 + SS*FF*6, Wp1 + SS*FF*3,
                              Wr1 + FF*FF, br1 + FF, Wr2g + FF*FF,
                              nullptr, positions, out);
}